// round 13
// baseline (speedup 1.0000x reference)
#include <cuda_runtime.h>
#include <cuda_fp16.h>
#include <cstdint>
#include <math.h>

#define N 8192
#define S1 8            // j-splits per pass
#define NIB 64          // i-blocks of 128 rows
#define JR 1024         // j per CTA per pass
#define KT 128          // j staged per B tile
#define NT 8            // tiles per pass (JR/KT)
#define RS 272          // B row stride bytes (128*2 + 16)

// -------- scratch (static device globals; no allocation) --------
__device__ __half   g_y1h[(size_t)32*N];            // [n][j]
__device__ __half   g_y2h[(size_t)8*N];             // [n][j]
__device__ uint32_t g_W[(size_t)256*64*8*16];       // [chunk][ib][warp][m] ballot words, 8MB
__device__ int      g_cntM[(size_t)S1*N];           // partial row counts
__device__ float    g_invrow[N];
__device__ float    g_part1[(size_t)S1*N*32];       // fp32 partials, 8MB
__device__ float    g_part2[(size_t)S1*N*8];

// ===================== helpers =====================
__device__ __forceinline__ uint32_t smem_u32(const void* p) {
    uint32_t a;
    asm("{ .reg .u64 t; cvta.to.shared.u64 t, %1; cvt.u32.u64 %0, t; }" : "=r"(a) : "l"(p));
    return a;
}
// expand 2 mask bits -> packed fp16x2 {bit0 ? 1.0 : 0, bit1 ? 1.0 : 0}
__device__ __forceinline__ uint32_t amask(uint32_t v) {
    return (v & 1u)*0x3C00u + ((v >> 1) & 1u)*0x3C000000u;
}
#define MMA16816(d, a, b0v, b1v) asm volatile( \
    "mma.sync.aligned.m16n8k16.row.col.f32.f16.f16.f32 " \
    "{%0,%1,%2,%3}, {%4,%5,%6,%7}, {%8,%9}, {%0,%1,%2,%3};" \
    : "+f"((d)[0]),"+f"((d)[1]),"+f"((d)[2]),"+f"((d)[3]) \
    : "r"((a)[0]),"r"((a)[1]),"r"((a)[2]),"r"((a)[3]), "r"(b0v),"r"(b1v))
#define LDSM_X4(r0,r1,r2,r3, addr) asm volatile( \
    "ldmatrix.sync.aligned.m8n8.x4.shared.b16 {%0,%1,%2,%3}, [%4];" \
    : "=r"(r0),"=r"(r1),"=r"(r2),"=r"(r3) : "r"(addr))

// ---------------- kernel 1: features + y1 = x@W1 + b1 -> fp16 [n][j] ----------------
__global__ void feat_kernel(const float4* __restrict__ led, const float* __restrict__ B,
                            const float* __restrict__ emb, const float* __restrict__ W1,
                            const float* __restrict__ b1) {
    __shared__ float sB[48], semb[104], sW1[40*32], sb1[32];
    int t = threadIdx.x;
    if (t < 48)  sB[t]   = B[t];
    if (t < 104) semb[t] = emb[t];
    if (t < 32)  sb1[t]  = b1[t];
    for (int idx = t; idx < 40*32; idx += 128) sW1[idx] = W1[idx];
    __syncthreads();

    int i = blockIdx.x*128 + t;
    float4 p = led[i];
    float x[40];
    #pragma unroll
    for (int f = 0; f < 16; f++) {
        float pr = (p.x*sB[f] + p.y*sB[16+f] + p.z*sB[32+f]) * 6.283185307179586f;
        float sv, cv; sincosf(pr, &sv, &cv);
        x[f] = sv; x[16+f] = cv;
    }
    int fr = (int)p.w;
    #pragma unroll
    for (int e = 0; e < 8; e++) x[32+e] = semb[fr*8 + e];

    #pragma unroll 4
    for (int k = 0; k < 32; k++) {
        float acc = sb1[k];
        #pragma unroll
        for (int d = 0; d < 40; d++) acc = fmaf(x[d], sW1[d*32 + k], acc);
        g_y1h[(size_t)k*N + i] = __float2half(acc);
    }
}

// ---------------- kernel 2: pass 1 — fused ballot-mask + HMMA GEMM (n=32) ----------------
__global__ void __launch_bounds__(256, 4) pass1_mma(const float4* __restrict__ led) {
    __shared__ __align__(16) char sBh[32*RS];    // 8.5KB fp16 B tile
    __shared__ __align__(16) float4 s_pi[128];   // {x,y,z,cim} per CTA i-row

    int t = threadIdx.x, lane = t & 31, wid = t >> 5;
    int ib = blockIdx.x, s = blockIdx.y;
    int q = lane & 3, g = lane >> 2;
    int i0g = ib*128 + wid*16;        // warp's 16 i-rows
    int i0 = i0g + g;                 // fragment rows i0, i0+8

    // stage CTA's 128 i-positions with precomputed cim
    if (t < 128) {
        float4 p = led[ib*128 + t];
        p.w = 3.125f - 0.5f*fmaf(p.x, p.x, fmaf(p.y, p.y, p.z*p.z));
        s_pi[t] = p;
    }
    __syncthreads();

    int cnt = 0;
    float dacc[4][4] = {};

    int sel = lane >> 3, lrow = lane & 7;
    uint32_t hA = smem_u32(sBh) + (uint32_t)(((sel >> 1)*8 + lrow)*RS + (sel & 1)*16);
    uint32_t hB = hA + 16*RS;
    const float4* s_prow = &s_pi[wid*16];

    for (int tile = 0; tile < NT; tile++) {
        int j0 = s*JR + tile*KT;
        __syncthreads();
        // stage B: 32 rows x 256B = 512 uint4, 2 per thread
        #pragma unroll
        for (int r2 = 0; r2 < 2; r2++) {
            int c = t + r2*256;
            int n = c >> 4, ch = c & 15;
            *(uint4*)(sBh + n*RS + ch*16) = *(const uint4*)(g_y1h + (size_t)n*N + j0 + ch*8);
        }
        __syncthreads();

        #pragma unroll
        for (int cc = 0; cc < 4; cc++) {
            int jb = j0 + cc*32;
            // ---- 16 predicate chains (independent), then 16 ballots ----
            float4 pj = led[jb + lane];
            float cj = -0.5f*fmaf(pj.x, pj.x, fmaf(pj.y, pj.y, pj.z*pj.z));
            float d[16];
            #pragma unroll
            for (int m = 0; m < 16; m++) {
                float4 pm = s_prow[m];
                d[m] = fmaf(pj.x, pm.x, fmaf(pj.y, pm.y, fmaf(pj.z, pm.z, pm.w + cj)));
            }
            uint32_t myW = 0;
            #pragma unroll
            for (int m = 0; m < 16; m++) {
                unsigned Wm = __ballot_sync(0xffffffffu, d[m] > 0.0f);
                if (lane == m) myW = Wm;
            }
            if (lane < 16) {
                cnt += __popc(myW);
                g_W[(((size_t)(jb >> 5)*64 + ib)*8 + wid)*16 + lane] = myW;
            }
            uint32_t Wg  = __shfl_sync(0xffffffffu, myW, g);
            uint32_t Wg8 = __shfl_sync(0xffffffffu, myW, g + 8);

            // ---- 2 kc of HMMA fed by the fresh bits ----
            #pragma unroll
            for (int hc = 0; hc < 2; hc++) {
                uint32_t vg  = Wg  >> (hc*16 + 2*q);
                uint32_t vg8 = Wg8 >> (hc*16 + 2*q);
                uint32_t a[4] = { amask(vg), amask(vg8), amask(vg >> 8), amask(vg8 >> 8) };

                uint32_t koff = (uint32_t)((cc*2 + hc)*32);
                uint32_t h0,h1,h2,h3, h4,h5,h6,h7;
                LDSM_X4(h0,h1,h2,h3, hA + koff);
                LDSM_X4(h4,h5,h6,h7, hB + koff);
                MMA16816(dacc[0], a, h0, h1);
                MMA16816(dacc[1], a, h2, h3);
                MMA16816(dacc[2], a, h4, h5);
                MMA16816(dacc[3], a, h6, h7);
            }
        }
    }

    float* d0 = &g_part1[((size_t)s*N + i0)*32];
    float* d1 = d0 + 8*32;
    #pragma unroll
    for (int m = 0; m < 4; m++) {
        *(float2*)(d0 + 8*m + 2*q) = make_float2(dacc[m][0], dacc[m][1]);
        *(float2*)(d1 + 8*m + 2*q) = make_float2(dacc[m][2], dacc[m][3]);
    }
    if (lane < 16) g_cntM[(size_t)s*N + i0g + lane] = cnt;
}

// ---------------- kernel 3: reduce -> h -> y2 -> fp16 [n][j] ----------------
__global__ void reduce1_y2(const float* __restrict__ W2, const float* __restrict__ b2) {
    __shared__ float sh[256];
    int t = threadIdx.x, b = blockIdx.x;
    int idx = b*256 + t;           // N*32 total
    int i = idx >> 5, k = idx & 31;
    float sum = 0.0f;
    #pragma unroll
    for (int s = 0; s < S1; s++) sum += g_part1[(size_t)s*N*32 + idx];
    int c = 0;
    #pragma unroll
    for (int s = 0; s < S1; s++) c += g_cntM[(size_t)s*N + i];
    float inv = 1.0f / ((float)c + 1e-6f);
    float h = sum * inv;
    sh[t] = h > 0.0f ? h : 0.0f;
    if (k == 0) g_invrow[i] = inv;
    __syncthreads();

    if (t < 64) {
        int row = t >> 3, kk = t & 7;
        float a = b2[kk];
        #pragma unroll
        for (int d = 0; d < 32; d++) a = fmaf(sh[row*32 + d], W2[d*8 + kk], a);
        g_y2h[(size_t)kk*N + b*8 + row] = __float2half(a);
    }
}

// ---------------- kernel 4: pass 2 — HMMA masked GEMM (n=8), bit-fed ----------------
__global__ void __launch_bounds__(256, 4) pass2_mma() {
    __shared__ __align__(16) char sBh[8*RS];

    int t = threadIdx.x, lane = t & 31, wid = t >> 5;
    int ib = blockIdx.x, s = blockIdx.y;
    int q = lane & 3, g = lane >> 2;
    int i0 = ib*128 + wid*16 + g;

    float dacc[4] = {};

    int sel = lane >> 3, lrow = lane & 7;
    uint32_t bAddr = smem_u32(sBh) + (uint32_t)(lrow*RS + sel*16);

    for (int tile = 0; tile < NT; tile++) {
        int j0 = s*JR + tile*KT;
        int c0 = j0 >> 5;
        __syncthreads();
        if (t < 128) {
            int n = t >> 4, ch = t & 15;
            *(uint4*)(sBh + n*RS + ch*16) = *(const uint4*)(g_y2h + (size_t)n*N + j0 + ch*8);
        }
        __syncthreads();

        uint32_t wg[4], wg8[4];
        #pragma unroll
        for (int cc = 0; cc < 4; cc++) {
            size_t base = (((size_t)(c0 + cc)*64 + ib)*8 + wid)*16;
            wg[cc]  = g_W[base + g];
            wg8[cc] = g_W[base + g + 8];
        }

        #pragma unroll
        for (int cc = 0; cc < 4; cc++) {
            uint32_t r0, r1, r2, r3;
            LDSM_X4(r0, r1, r2, r3, bAddr + (uint32_t)(cc*64));
            #pragma unroll
            for (int hc = 0; hc < 2; hc++) {
                uint32_t vg  = wg[cc]  >> (hc*16 + 2*q);
                uint32_t vg8 = wg8[cc] >> (hc*16 + 2*q);
                uint32_t a[4] = { amask(vg), amask(vg8), amask(vg >> 8), amask(vg8 >> 8) };
                if (hc == 0) { MMA16816(dacc, a, r0, r1); }
                else         { MMA16816(dacc, a, r2, r3); }
            }
        }
    }

    float* d0 = &g_part2[((size_t)s*N + i0)*8];
    *(float2*)(d0 + 2*q)       = make_float2(dacc[0], dacc[1]);
    *(float2*)(d0 + 64 + 2*q)  = make_float2(dacc[2], dacc[3]);   // row i0+8
}

// ---------------- kernel 5: reduce + relu -> out ----------------
__global__ void reduce2_kernel(float* __restrict__ out) {
    int idx = blockIdx.x*256 + threadIdx.x;   // N*8
    int i = idx >> 3;
    float sum = 0.0f;
    #pragma unroll
    for (int s = 0; s < S1; s++) sum += g_part2[(size_t)s*N*8 + idx];
    float v = sum * g_invrow[i];
    out[idx] = v > 0.0f ? v : 0.0f;
}

// ---------------- launch ----------------
extern "C" void kernel_launch(void* const* d_in, const int* in_sizes, int n_in,
                              void* d_out, int out_size) {
    const float4* led = (const float4*)d_in[0];
    const float*  B   = (const float*)d_in[1];
    const float*  emb = (const float*)d_in[2];
    const float*  W1  = (const float*)d_in[3];
    const float*  b1  = (const float*)d_in[4];
    const float*  W2  = (const float*)d_in[5];
    const float*  b2  = (const float*)d_in[6];
    float* out = (float*)d_out;

    feat_kernel<<<64, 128>>>(led, B, emb, W1, b1);
    pass1_mma<<<dim3(NIB, S1), 256>>>(led);
    reduce1_y2<<<N*32/256, 256>>>(W2, b2);
    pass2_mma<<<dim3(NIB, S1), 256>>>();
    reduce2_kernel<<<N*8/256, 256>>>(out);
}

// round 14
// speedup vs baseline: 1.0970x; 1.0970x over previous
#include <cuda_runtime.h>
#include <cuda_fp16.h>
#include <cstdint>
#include <math.h>

#define N 8192
#define NIB 64          // i-blocks of 128 rows
// pass 1 config (R12-proven)
#define P1S 4
#define P1JR 2048
#define P1KT 256
#define P1NT 8
#define P1RS 528
// pass 2 config (R13-proven)
#define P2S 8
#define P2JR 1024
#define P2KT 128
#define P2NT 8
#define P2RS 272

// -------- scratch (static device globals; no allocation) --------
__device__ __half   g_y1h[(size_t)32*N];            // [n][j]
__device__ __half   g_y2h[(size_t)8*N];             // [n][j]
__device__ uint32_t g_W[(size_t)256*64*8*16];       // [chunk][ib][warp][m] ballot words, 8MB
__device__ int      g_cntM[(size_t)P1S*N];          // partial row counts
__device__ float    g_invrow[N];
__device__ float    g_part1[(size_t)P1S*N*32];      // fp32 partials, 4MB
__device__ float    g_part2[(size_t)P2S*N*8];

// ===================== helpers =====================
__device__ __forceinline__ uint32_t smem_u32(const void* p) {
    uint32_t a;
    asm("{ .reg .u64 t; cvta.to.shared.u64 t, %1; cvt.u32.u64 %0, t; }" : "=r"(a) : "l"(p));
    return a;
}
// expand 2 mask bits -> packed fp16x2 {bit0 ? 1.0 : 0, bit1 ? 1.0 : 0}
__device__ __forceinline__ uint32_t amask(uint32_t v) {
    return (v & 1u)*0x3C00u + ((v >> 1) & 1u)*0x3C000000u;
}
#define MMA16816(d, a, b0v, b1v) asm volatile( \
    "mma.sync.aligned.m16n8k16.row.col.f32.f16.f16.f32 " \
    "{%0,%1,%2,%3}, {%4,%5,%6,%7}, {%8,%9}, {%0,%1,%2,%3};" \
    : "+f"((d)[0]),"+f"((d)[1]),"+f"((d)[2]),"+f"((d)[3]) \
    : "r"((a)[0]),"r"((a)[1]),"r"((a)[2]),"r"((a)[3]), "r"(b0v),"r"(b1v))
#define LDSM_X4(r0,r1,r2,r3, addr) asm volatile( \
    "ldmatrix.sync.aligned.m8n8.x4.shared.b16 {%0,%1,%2,%3}, [%4];" \
    : "=r"(r0),"=r"(r1),"=r"(r2),"=r"(r3) : "r"(addr))

// ---------------- kernel 1: features + y1 = x@W1 + b1 -> fp16 [n][j] ----------------
__global__ void feat_kernel(const float4* __restrict__ led, const float* __restrict__ B,
                            const float* __restrict__ emb, const float* __restrict__ W1,
                            const float* __restrict__ b1) {
    __shared__ float sB[48], semb[104], sW1[40*32], sb1[32];
    int t = threadIdx.x;
    if (t < 48)  sB[t]   = B[t];
    if (t < 104) semb[t] = emb[t];
    if (t < 32)  sb1[t]  = b1[t];
    for (int idx = t; idx < 40*32; idx += 128) sW1[idx] = W1[idx];
    __syncthreads();

    int i = blockIdx.x*128 + t;
    float4 p = led[i];
    float x[40];
    #pragma unroll
    for (int f = 0; f < 16; f++) {
        float pr = (p.x*sB[f] + p.y*sB[16+f] + p.z*sB[32+f]) * 6.283185307179586f;
        float sv, cv; sincosf(pr, &sv, &cv);
        x[f] = sv; x[16+f] = cv;
    }
    int fr = (int)p.w;
    #pragma unroll
    for (int e = 0; e < 8; e++) x[32+e] = semb[fr*8 + e];

    #pragma unroll 4
    for (int k = 0; k < 32; k++) {
        float acc = sb1[k];
        #pragma unroll
        for (int d = 0; d < 40; d++) acc = fmaf(x[d], sW1[d*32 + k], acc);
        g_y1h[(size_t)k*N + i] = __float2half(acc);
    }
}

// ---------------- kernel 2: pass 1 — fused ballot-mask + HMMA GEMM (n=32) [R12 config] ----------------
__global__ void __launch_bounds__(256, 2) pass1_mma(const float4* __restrict__ led) {
    __shared__ __align__(16) char sBh[32*P1RS];   // 16.9KB fp16 B tile

    int t = threadIdx.x, lane = t & 31, wid = t >> 5;
    int ib = blockIdx.x, s = blockIdx.y;
    int q = lane & 3, g = lane >> 2;
    int i0g = ib*128 + wid*16;        // warp's 16 i-rows
    int i0 = i0g + g;                 // fragment rows i0, i0+8

    // warp's row positions in registers
    float px[16], py[16], pz[16], cim[16];
    #pragma unroll
    for (int m = 0; m < 16; m++) {
        float4 p = led[i0g + m];
        px[m] = p.x; py[m] = p.y; pz[m] = p.z;
        cim[m] = 3.125f - 0.5f*fmaf(p.x, p.x, fmaf(p.y, p.y, p.z*p.z));
    }
    int cnt = 0;
    float dacc[4][4] = {};

    int sel = lane >> 3, lrow = lane & 7;
    uint32_t hA = smem_u32(sBh) + (uint32_t)(((sel >> 1)*8 + lrow)*P1RS + (sel & 1)*16);
    uint32_t hB = hA + 16*P1RS;

    for (int tile = 0; tile < P1NT; tile++) {
        int j0 = s*P1JR + tile*P1KT;
        __syncthreads();
        // stage B: 32 rows x 512B = 1024 uint4, 4 per thread
        #pragma unroll
        for (int r2 = 0; r2 < 4; r2++) {
            int c = t + r2*256;
            int n = c >> 5, ch = c & 31;
            *(uint4*)(sBh + n*P1RS + ch*16) = *(const uint4*)(g_y1h + (size_t)n*N + j0 + ch*8);
        }
        __syncthreads();

        #pragma unroll
        for (int cc = 0; cc < 8; cc++) {
            int jb = j0 + cc*32;
            // ---- 16 ballots interleaved with predicate chains ----
            float4 pj = led[jb + lane];
            float cj = -0.5f*fmaf(pj.x, pj.x, fmaf(pj.y, pj.y, pj.z*pj.z));
            uint32_t myW = 0;
            #pragma unroll
            for (int m = 0; m < 16; m++) {
                float d = fmaf(pj.x, px[m], fmaf(pj.y, py[m], fmaf(pj.z, pz[m], cim[m] + cj)));
                unsigned Wm = __ballot_sync(0xffffffffu, d > 0.0f);
                if (lane == m) myW = Wm;
            }
            if (lane < 16) {
                cnt += __popc(myW);
                g_W[(((size_t)(jb >> 5)*64 + ib)*8 + wid)*16 + lane] = myW;
            }
            uint32_t Wg  = __shfl_sync(0xffffffffu, myW, g);
            uint32_t Wg8 = __shfl_sync(0xffffffffu, myW, g + 8);

            // ---- 2 kc of HMMA fed by the fresh bits ----
            #pragma unroll
            for (int hc = 0; hc < 2; hc++) {
                uint32_t vg  = Wg  >> (hc*16 + 2*q);
                uint32_t vg8 = Wg8 >> (hc*16 + 2*q);
                uint32_t a[4] = { amask(vg), amask(vg8), amask(vg >> 8), amask(vg8 >> 8) };

                uint32_t koff = (uint32_t)((cc*2 + hc)*32);
                uint32_t h0,h1,h2,h3, h4,h5,h6,h7;
                LDSM_X4(h0,h1,h2,h3, hA + koff);
                LDSM_X4(h4,h5,h6,h7, hB + koff);
                MMA16816(dacc[0], a, h0, h1);
                MMA16816(dacc[1], a, h2, h3);
                MMA16816(dacc[2], a, h4, h5);
                MMA16816(dacc[3], a, h6, h7);
            }
        }
    }

    float* d0 = &g_part1[((size_t)s*N + i0)*32];
    float* d1 = d0 + 8*32;
    #pragma unroll
    for (int m = 0; m < 4; m++) {
        *(float2*)(d0 + 8*m + 2*q) = make_float2(dacc[m][0], dacc[m][1]);
        *(float2*)(d1 + 8*m + 2*q) = make_float2(dacc[m][2], dacc[m][3]);
    }
    if (lane < 16) g_cntM[(size_t)s*N + i0g + lane] = cnt;
}

// ---------------- kernel 3: reduce -> h -> y2 -> fp16 [n][j] ----------------
__global__ void reduce1_y2(const float* __restrict__ W2, const float* __restrict__ b2) {
    __shared__ float sh[256];
    int t = threadIdx.x, b = blockIdx.x;
    int idx = b*256 + t;           // N*32 total
    int i = idx >> 5, k = idx & 31;
    float sum = 0.0f;
    #pragma unroll
    for (int s = 0; s < P1S; s++) sum += g_part1[(size_t)s*N*32 + idx];
    int c = 0;
    #pragma unroll
    for (int s = 0; s < P1S; s++) c += g_cntM[(size_t)s*N + i];
    float inv = 1.0f / ((float)c + 1e-6f);
    float h = sum * inv;
    sh[t] = h > 0.0f ? h : 0.0f;
    if (k == 0) g_invrow[i] = inv;
    __syncthreads();

    if (t < 64) {
        int row = t >> 3, kk = t & 7;
        float a = b2[kk];
        #pragma unroll
        for (int d = 0; d < 32; d++) a = fmaf(sh[row*32 + d], W2[d*8 + kk], a);
        g_y2h[(size_t)kk*N + b*8 + row] = __float2half(a);
    }
}

// ---------------- kernel 4: pass 2 — HMMA masked GEMM (n=8), bit-fed [R13 config + W prefetch] ----------------
__global__ void __launch_bounds__(256, 4) pass2_mma() {
    __shared__ __align__(16) char sBh[8*P2RS];

    int t = threadIdx.x, lane = t & 31, wid = t >> 5;
    int ib = blockIdx.x, s = blockIdx.y;
    int q = lane & 3, g = lane >> 2;
    int i0 = ib*128 + wid*16 + g;

    float dacc[4] = {};

    int sel = lane >> 3, lrow = lane & 7;
    uint32_t bAddr = smem_u32(sBh) + (uint32_t)(lrow*P2RS + sel*16);

    for (int tile = 0; tile < P2NT; tile++) {
        int j0 = s*P2JR + tile*P2KT;
        int c0 = j0 >> 5;

        // prefetch W words (GMEM only — overlaps the barrier wait below)
        uint32_t wg[4], wg8[4];
        #pragma unroll
        for (int cc = 0; cc < 4; cc++) {
            size_t base = (((size_t)(c0 + cc)*64 + ib)*8 + wid)*16;
            wg[cc]  = g_W[base + g];
            wg8[cc] = g_W[base + g + 8];
        }

        __syncthreads();
        if (t < 128) {
            int n = t >> 4, ch = t & 15;
            *(uint4*)(sBh + n*P2RS + ch*16) = *(const uint4*)(g_y2h + (size_t)n*N + j0 + ch*8);
        }
        __syncthreads();

        #pragma unroll
        for (int cc = 0; cc < 4; cc++) {
            uint32_t r0, r1, r2, r3;
            LDSM_X4(r0, r1, r2, r3, bAddr + (uint32_t)(cc*64));
            #pragma unroll
            for (int hc = 0; hc < 2; hc++) {
                uint32_t vg  = wg[cc]  >> (hc*16 + 2*q);
                uint32_t vg8 = wg8[cc] >> (hc*16 + 2*q);
                uint32_t a[4] = { amask(vg), amask(vg8), amask(vg >> 8), amask(vg8 >> 8) };
                if (hc == 0) { MMA16816(dacc, a, r0, r1); }
                else         { MMA16816(dacc, a, r2, r3); }
            }
        }
    }

    float* d0 = &g_part2[((size_t)s*N + i0)*8];
    *(float2*)(d0 + 2*q)       = make_float2(dacc[0], dacc[1]);
    *(float2*)(d0 + 64 + 2*q)  = make_float2(dacc[2], dacc[3]);   // row i0+8
}

// ---------------- kernel 5: reduce + relu -> out ----------------
__global__ void reduce2_kernel(float* __restrict__ out) {
    int idx = blockIdx.x*256 + threadIdx.x;   // N*8
    int i = idx >> 3;
    float sum = 0.0f;
    #pragma unroll
    for (int s = 0; s < P2S; s++) sum += g_part2[(size_t)s*N*8 + idx];
    float v = sum * g_invrow[i];
    out[idx] = v > 0.0f ? v : 0.0f;
}

// ---------------- launch ----------------
extern "C" void kernel_launch(void* const* d_in, const int* in_sizes, int n_in,
                              void* d_out, int out_size) {
    const float4* led = (const float4*)d_in[0];
    const float*  B   = (const float*)d_in[1];
    const float*  emb = (const float*)d_in[2];
    const float*  W1  = (const float*)d_in[3];
    const float*  b1  = (const float*)d_in[4];
    const float*  W2  = (const float*)d_in[5];
    const float*  b2  = (const float*)d_in[6];
    float* out = (float*)d_out;

    feat_kernel<<<64, 128>>>(led, B, emb, W1, b1);
    pass1_mma<<<dim3(NIB, P1S), 256>>>(led);
    reduce1_y2<<<N*32/256, 256>>>(W2, b2);
    pass2_mma<<<dim3(NIB, P2S), 256>>>();
    reduce2_kernel<<<N*8/256, 256>>>(out);
}